// round 1
// baseline (speedup 1.0000x reference)
#include <cuda_runtime.h>

// SSIM loss over (32,1,512,512) fp32 pairs.
// Key facts: reference's sigma1/sigma2 are dead code -> only conv(x), conv(y),
// conv(x*y) are needed. Gaussian window is separable (outer(g,g) of normalized g).
//
// Kernel 1: per 32x32 tile (+5 halo): stage x,y,x*y in shared, horizontal 11-tap
//           pass (float4 register sliding window), vertical 11-tap pass in
//           registers, per-pixel SSIM, block-sum -> partial per block.
// Kernel 2: reduce 8192 partials -> mean scalar.

#define TS 32
#define HALO 5
#define S 42            // TS + 2*HALO
#define SPITCH 44       // padded row pitch for input stage (multiple of 4)
#define IMG 512
#define NIMG 32
#define NTILE 16        // 512/32
#define NBLK (NIMG * NTILE * NTILE)   // 8192

__device__ float g_partials[NBLK];

// Normalized 1D Gaussian, window 11, sigma 1.5 (double-precision derived).
#define W0 0.00102838f
#define W1 0.00759876f
#define W2 0.03600077f
#define W3 0.10936060f
#define W4 0.21300553f
#define W5 0.26601172f

__constant__ float c_unused; // keep constant bank alive (no-op)

__global__ __launch_bounds__(256, 3)
void ssim_tile_kernel(const float* __restrict__ X, const float* __restrict__ Y)
{
    __shared__ float sx[S][SPITCH];
    __shared__ float sy[S][SPITCH];
    __shared__ float sp[S][SPITCH];
    __shared__ float hx[S][TS];
    __shared__ float hy[S][TS];
    __shared__ float hp[S][TS];
    __shared__ float wsum[8];

    const float WG[11] = {W0, W1, W2, W3, W4, W5, W4, W3, W2, W1, W0};

    const int tid  = threadIdx.x;
    const int img  = blockIdx.z;
    const int row0 = blockIdx.y * TS - HALO;
    const int col0 = blockIdx.x * TS - HALO;

    const float* __restrict__ Xi = X + (size_t)img * IMG * IMG;
    const float* __restrict__ Yi = Y + (size_t)img * IMG * IMG;

    // ---- Stage inputs (zero padding outside image) ----
    #pragma unroll 1
    for (int i = tid; i < S * S; i += 256) {
        int r = i / S;
        int c = i - r * S;
        int gr = row0 + r;
        int gc = col0 + c;
        float xv = 0.0f, yv = 0.0f;
        if ((unsigned)gr < (unsigned)IMG && (unsigned)gc < (unsigned)IMG) {
            xv = __ldg(&Xi[gr * IMG + gc]);
            yv = __ldg(&Yi[gr * IMG + gc]);
        }
        sx[r][c] = xv;
        sy[r][c] = yv;
        sp[r][c] = xv * yv;
    }
    __syncthreads();

    // ---- Horizontal 11-tap pass: each position = (row r, quad q) -> 4 outputs.
    // Load 16 floats (4x float4), compute outs c0..c0+3 from in c0..c0+13.
    #pragma unroll 1
    for (int i = tid; i < S * 8; i += 256) {
        int r  = i >> 3;
        int q  = i & 7;
        int c0 = q * 4;

        // channel X
        {
            float4 a = *(const float4*)&sx[r][c0];
            float4 b = *(const float4*)&sx[r][c0 + 4];
            float4 cc = *(const float4*)&sx[r][c0 + 8];
            float4 dd = *(const float4*)&sx[r][c0 + 12];
            float in[16] = {a.x,a.y,a.z,a.w, b.x,b.y,b.z,b.w,
                            cc.x,cc.y,cc.z,cc.w, dd.x,dd.y,dd.z,dd.w};
            float4 o;
            float* op = &o.x;
            #pragma unroll
            for (int j = 0; j < 4; j++) {
                float acc = 0.0f;
                #pragma unroll
                for (int k = 0; k < 11; k++) acc += WG[k] * in[j + k];
                op[j] = acc;
            }
            *(float4*)&hx[r][c0] = o;
        }
        // channel Y
        {
            float4 a = *(const float4*)&sy[r][c0];
            float4 b = *(const float4*)&sy[r][c0 + 4];
            float4 cc = *(const float4*)&sy[r][c0 + 8];
            float4 dd = *(const float4*)&sy[r][c0 + 12];
            float in[16] = {a.x,a.y,a.z,a.w, b.x,b.y,b.z,b.w,
                            cc.x,cc.y,cc.z,cc.w, dd.x,dd.y,dd.z,dd.w};
            float4 o;
            float* op = &o.x;
            #pragma unroll
            for (int j = 0; j < 4; j++) {
                float acc = 0.0f;
                #pragma unroll
                for (int k = 0; k < 11; k++) acc += WG[k] * in[j + k];
                op[j] = acc;
            }
            *(float4*)&hy[r][c0] = o;
        }
        // channel X*Y
        {
            float4 a = *(const float4*)&sp[r][c0];
            float4 b = *(const float4*)&sp[r][c0 + 4];
            float4 cc = *(const float4*)&sp[r][c0 + 8];
            float4 dd = *(const float4*)&sp[r][c0 + 12];
            float in[16] = {a.x,a.y,a.z,a.w, b.x,b.y,b.z,b.w,
                            cc.x,cc.y,cc.z,cc.w, dd.x,dd.y,dd.z,dd.w};
            float4 o;
            float* op = &o.x;
            #pragma unroll
            for (int j = 0; j < 4; j++) {
                float acc = 0.0f;
                #pragma unroll
                for (int k = 0; k < 11; k++) acc += WG[k] * in[j + k];
                op[j] = acc;
            }
            *(float4*)&hp[r][c0] = o;
        }
    }
    __syncthreads();

    // ---- Vertical 11-tap pass + SSIM. Thread = column c, 4 output rows. ----
    const int c  = tid & 31;
    const int r0 = (tid >> 5) * 4;

    float vx[14], vy[14], vp[14];
    #pragma unroll
    for (int m = 0; m < 14; m++) {
        vx[m] = hx[r0 + m][c];
        vy[m] = hy[r0 + m][c];
        vp[m] = hp[r0 + m][c];
    }

    const float C1 = 0.0001f;   // 0.01^2
    const float C2 = 0.0009f;   // 0.03^2

    float lsum = 0.0f;
    #pragma unroll
    for (int j = 0; j < 4; j++) {
        float mu1 = 0.0f, mu2 = 0.0f, mxy = 0.0f;
        #pragma unroll
        for (int k = 0; k < 11; k++) {
            mu1 += WG[k] * vx[j + k];
            mu2 += WG[k] * vy[j + k];
            mxy += WG[k] * vp[j + k];
        }
        float m12 = mu1 * mu2;
        float sig = mxy - m12;                 // sigma_xy
        float sq  = mu1 * mu1 + mu2 * mu2;     // mu1^2 + mu2^2
        float num = (2.0f * m12 + C1) * (2.0f * sig + C2);
        float den = (sq + C1) * (sq + C2);
        lsum += num / den;
    }

    // ---- Block reduction (deterministic; no fp atomics) ----
    #pragma unroll
    for (int off = 16; off > 0; off >>= 1)
        lsum += __shfl_xor_sync(0xFFFFFFFFu, lsum, off);
    if ((tid & 31) == 0) wsum[tid >> 5] = lsum;
    __syncthreads();
    if (tid < 32) {
        float v = (tid < 8) ? wsum[tid] : 0.0f;
        #pragma unroll
        for (int off = 4; off > 0; off >>= 1)
            v += __shfl_xor_sync(0xFFFFFFFFu, v, off);
        if (tid == 0) {
            int bid = (blockIdx.z * gridDim.y + blockIdx.y) * gridDim.x + blockIdx.x;
            g_partials[bid] = v;
        }
    }
}

__global__ __launch_bounds__(256)
void ssim_reduce_kernel(float* __restrict__ out)
{
    __shared__ float wsum[8];
    const int tid = threadIdx.x;
    float s = 0.0f;
    #pragma unroll 4
    for (int i = tid; i < NBLK; i += 256) s += g_partials[i];
    #pragma unroll
    for (int off = 16; off > 0; off >>= 1)
        s += __shfl_xor_sync(0xFFFFFFFFu, s, off);
    if ((tid & 31) == 0) wsum[tid >> 5] = s;
    __syncthreads();
    if (tid < 32) {
        float v = (tid < 8) ? wsum[tid] : 0.0f;
        #pragma unroll
        for (int off = 4; off > 0; off >>= 1)
            v += __shfl_xor_sync(0xFFFFFFFFu, v, off);
        if (tid == 0)
            out[0] = v * (1.0f / 8388608.0f);   // mean over 32*512*512
    }
}

extern "C" void kernel_launch(void* const* d_in, const int* in_sizes, int n_in,
                              void* d_out, int out_size)
{
    (void)in_sizes; (void)n_in; (void)out_size;
    const float* X_gt   = (const float*)d_in[0];
    const float* X_pred = (const float*)d_in[1];
    float* out = (float*)d_out;

    dim3 grid(NTILE, NTILE, NIMG);
    ssim_tile_kernel<<<grid, 256>>>(X_gt, X_pred);
    ssim_reduce_kernel<<<1, 256>>>(out);
}

// round 2
// speedup vs baseline: 1.1716x; 1.1716x over previous
#include <cuda_runtime.h>

// SSIM loss, (32,1,512,512) fp32. Single fused kernel.
// - reference's sigma1/sigma2 are dead code -> need conv(x), conv(y), conv(x*y) only
// - separable 11-tap Gaussian: horizontal pass into shared h-buffers, vertical in regs
// - x*y computed in registers during horizontal pass (never staged)
// - tile 64x32 processed as two 32-wide halves to keep static smem < 48KB
// - grid-wide mean via last-block ticket reduction (deterministic order)

#define IMG    512
#define TW     64        // tile width
#define TH     32        // tile height
#define HW     32        // half width
#define SR     42        // staged rows  (TH + 10)
#define SC     74        // staged cols  (TW + 10)
#define PITCH  76        // stage pitch (float4-aligned)
#define HPITCH 36        // h-buffer pitch (36%32=4 -> conflict-free f4 stores)
#define GX     8
#define GY     16
#define GZ     32
#define NBLK   (GX * GY * GZ)   // 4096

__device__ float        g_partials[NBLK];
__device__ unsigned int g_count;   // zero-initialized; self-resets each call

// normalized 1D Gaussian, K=11, sigma=1.5
#define W0 0.00102838f
#define W1 0.00759876f
#define W2 0.03600077f
#define W3 0.10936060f
#define W4 0.21300553f
#define W5 0.26601172f

__global__ __launch_bounds__(256, 2)
void ssim_fused_kernel(const float* __restrict__ X, const float* __restrict__ Y,
                       float* __restrict__ out)
{
    __shared__ float sx[SR][PITCH];
    __shared__ float sy[SR][PITCH];
    __shared__ float hx[SR][HPITCH];
    __shared__ float hy[SR][HPITCH];
    __shared__ float hp[SR][HPITCH];
    __shared__ float wsum[8];
    __shared__ int   s_last;

    const float WG[11] = {W0, W1, W2, W3, W4, W5, W4, W3, W2, W1, W0};

    const int tid  = threadIdx.x;
    const int img  = blockIdx.z;
    const int row0 = blockIdx.y * TH - 5;
    const int col0 = blockIdx.x * TW - 5;

    const float* __restrict__ Xi = X + (size_t)img * IMG * IMG;
    const float* __restrict__ Yi = Y + (size_t)img * IMG * IMG;

    // ---------- stage x, y (zero padding outside image) ----------
    #pragma unroll 1
    for (int i = tid; i < SR * SC; i += 256) {
        int r  = i / SC;
        int c  = i - r * SC;
        int gr = row0 + r;
        int gc = col0 + c;
        float xv = 0.0f, yv = 0.0f;
        if ((unsigned)gr < (unsigned)IMG && (unsigned)gc < (unsigned)IMG) {
            xv = __ldg(&Xi[gr * IMG + gc]);
            yv = __ldg(&Yi[gr * IMG + gc]);
        }
        sx[r][c] = xv;
        sy[r][c] = yv;
    }
    __syncthreads();

    const float C1 = 0.0001f;   // 0.01^2
    const float C2 = 0.0009f;   // 0.03^2
    float lsum = 0.0f;

    #pragma unroll 1
    for (int half = 0; half < 2; half++) {
        const int cbase = half * HW;

        // ---------- horizontal 11-tap pass: 168 items x 8 outputs ----------
        if (tid < SR * 4) {
            int r  = tid >> 2;
            int o  = tid & 3;
            int c0 = o * 8;
            const float* px = &sx[r][cbase + c0];
            const float* py = &sy[r][cbase + c0];

            float xv[20], yv[20];
            #pragma unroll
            for (int q = 0; q < 5; q++) {
                float4 a = *(const float4*)(px + 4 * q);
                float4 b = *(const float4*)(py + 4 * q);
                xv[4*q+0] = a.x; xv[4*q+1] = a.y; xv[4*q+2] = a.z; xv[4*q+3] = a.w;
                yv[4*q+0] = b.x; yv[4*q+1] = b.y; yv[4*q+2] = b.z; yv[4*q+3] = b.w;
            }
            float pv[18];
            #pragma unroll
            for (int m = 0; m < 18; m++) pv[m] = xv[m] * yv[m];

            float ox[8], oy[8], op[8];
            #pragma unroll
            for (int j = 0; j < 8; j++) {
                float ax = 0.0f, ay = 0.0f, ap = 0.0f;
                #pragma unroll
                for (int k = 0; k < 11; k++) {
                    ax += WG[k] * xv[j + k];
                    ay += WG[k] * yv[j + k];
                    ap += WG[k] * pv[j + k];
                }
                ox[j] = ax; oy[j] = ay; op[j] = ap;
            }
            *(float4*)&hx[r][c0]     = make_float4(ox[0], ox[1], ox[2], ox[3]);
            *(float4*)&hx[r][c0 + 4] = make_float4(ox[4], ox[5], ox[6], ox[7]);
            *(float4*)&hy[r][c0]     = make_float4(oy[0], oy[1], oy[2], oy[3]);
            *(float4*)&hy[r][c0 + 4] = make_float4(oy[4], oy[5], oy[6], oy[7]);
            *(float4*)&hp[r][c0]     = make_float4(op[0], op[1], op[2], op[3]);
            *(float4*)&hp[r][c0 + 4] = make_float4(op[4], op[5], op[6], op[7]);
        }
        __syncthreads();

        // ---------- vertical 11-tap pass + SSIM: 32 cols x 8 groups x 4 rows ----------
        {
            const int c   = tid & 31;
            const int r0v = (tid >> 5) * 4;

            float vx[14], vy[14], vp[14];
            #pragma unroll
            for (int m = 0; m < 14; m++) {
                vx[m] = hx[r0v + m][c];
                vy[m] = hy[r0v + m][c];
                vp[m] = hp[r0v + m][c];
            }
            #pragma unroll
            for (int j = 0; j < 4; j++) {
                float mu1 = 0.0f, mu2 = 0.0f, mxy = 0.0f;
                #pragma unroll
                for (int k = 0; k < 11; k++) {
                    mu1 += WG[k] * vx[j + k];
                    mu2 += WG[k] * vy[j + k];
                    mxy += WG[k] * vp[j + k];
                }
                float m12 = mu1 * mu2;
                float sig = mxy - m12;
                float sq  = mu1 * mu1 + mu2 * mu2;
                float num = (2.0f * m12 + C1) * (2.0f * sig + C2);
                float den = (sq + C1) * (sq + C2);
                lsum += __fdividef(num, den);
            }
        }
        __syncthreads();
    }

    // ---------- block reduction ----------
    #pragma unroll
    for (int off = 16; off > 0; off >>= 1)
        lsum += __shfl_xor_sync(0xFFFFFFFFu, lsum, off);
    if ((tid & 31) == 0) wsum[tid >> 5] = lsum;
    __syncthreads();
    if (tid == 0) {
        float v = 0.0f;
        #pragma unroll
        for (int w = 0; w < 8; w++) v += wsum[w];
        int bid = blockIdx.x + GX * (blockIdx.y + GY * blockIdx.z);
        g_partials[bid] = v;
        __threadfence();
        unsigned int ticket = atomicAdd(&g_count, 1u);
        s_last = (ticket == NBLK - 1);
    }
    __syncthreads();

    // ---------- last block: final deterministic reduction ----------
    if (s_last) {
        float s = 0.0f;
        #pragma unroll 4
        for (int i = tid; i < NBLK; i += 256)
            s += *((volatile float*)&g_partials[i]);
        #pragma unroll
        for (int off = 16; off > 0; off >>= 1)
            s += __shfl_xor_sync(0xFFFFFFFFu, s, off);
        __syncthreads();   // reuse wsum safely
        if ((tid & 31) == 0) wsum[tid >> 5] = s;
        __syncthreads();
        if (tid == 0) {
            float v = 0.0f;
            #pragma unroll
            for (int w = 0; w < 8; w++) v += wsum[w];
            out[0]  = v * (1.0f / 8388608.0f);   // mean over 32*512*512
            g_count = 0;                          // reset for next call
        }
    }
}

extern "C" void kernel_launch(void* const* d_in, const int* in_sizes, int n_in,
                              void* d_out, int out_size)
{
    (void)in_sizes; (void)n_in; (void)out_size;
    const float* X_gt   = (const float*)d_in[0];
    const float* X_pred = (const float*)d_in[1];
    float* out = (float*)d_out;

    dim3 grid(GX, GY, GZ);
    ssim_fused_kernel<<<grid, 256>>>(X_gt, X_pred, out);
}

// round 3
// speedup vs baseline: 1.3040x; 1.1130x over previous
#include <cuda_runtime.h>

// SSIM loss, (32,1,512,512) fp32. Single fused kernel, f32x2-packed FIR.
// - reference's sigma1/sigma2 are dead code -> conv(x), conv(y), conv(x*y) only
// - separable 11-tap Gaussian; (x,y) packed into f32x2 lanes -> fma.rn.f32x2
// - accumulator-stationary streaming FIR (low register pressure, 5 blocks/SM)
// - tile 64x32 as two 32-wide halves; grid mean via last-block ticket

#define IMG   512
#define TW    64
#define TH    32
#define SR    42          // TH + 10
#define SCF2  74          // staged cols as float2 (TW + 10)
#define SPIT  74          // stage pitch (f2) : 592B % 128 = 80 -> conflict-free
#define HPIT  38          // hxy pitch (f2)   : 304B % 128 = 48 -> conflict-free
#define PPIT  36          // hp  pitch (f32)  : 144B % 128 = 16 -> conflict-free
#define GX    8
#define GY    16
#define GZ    32
#define NBLK  (GX * GY * GZ)   // 4096

__device__ float        g_partials[NBLK];
__device__ unsigned int g_count;     // zero-init; self-resets

// normalized 1D Gaussian, K=11, sigma=1.5
#define W0 0.00102838f
#define W1 0.00759876f
#define W2 0.03600077f
#define W3 0.10936060f
#define W4 0.21300553f
#define W5 0.26601172f

#define FMA2(d, a, b, c) \
    asm("fma.rn.f32x2 %0, %1, %2, %3;" : "=l"(d) : "l"(a), "l"(b), "l"(c))
#define UNPK(lo, hi, v) \
    asm("mov.b64 {%0, %1}, %2;" : "=f"(lo), "=f"(hi) : "l"(v))

__device__ __forceinline__ unsigned long long pk2(float w) {
    unsigned long long r;
    asm("mov.b64 %0, {%1, %1};" : "=l"(r) : "f"(w));
    return r;
}

__global__ __launch_bounds__(256, 5)
void ssim_fused_kernel(const float* __restrict__ X, const float* __restrict__ Y,
                       float* __restrict__ out)
{
    __shared__ unsigned long long sxy[SR][SPIT];   // packed (x,y), 24.9KB
    __shared__ unsigned long long hxy[SR][HPIT];   // packed h-conv (x,y), 12.8KB
    __shared__ float              hp [SR][PPIT];   // h-conv of x*y, 6.05KB
    __shared__ float              wsum[8];
    __shared__ int                s_last;

    const float WGs[11] = {W0, W1, W2, W3, W4, W5, W4, W3, W2, W1, W0};
    const unsigned long long p0 = pk2(W0), p1 = pk2(W1), p2 = pk2(W2),
                             p3 = pk2(W3), p4 = pk2(W4), p5 = pk2(W5);
    const unsigned long long WP[11] = {p0,p1,p2,p3,p4,p5,p4,p3,p2,p1,p0};

    const int tid  = threadIdx.x;
    const int img  = blockIdx.z;
    const int row0 = blockIdx.y * TH - 5;
    const int col0 = blockIdx.x * TW - 5;

    const float* __restrict__ Xi = X + (size_t)img * IMG * IMG;
    const float* __restrict__ Yi = Y + (size_t)img * IMG * IMG;

    // ---------------- stage packed (x, y) ----------------
    const bool interior = (row0 >= 0) && (row0 + SR <= IMG) &&
                          (col0 >= 0) && (col0 + SCF2 <= IMG);
    if (interior) {
        #pragma unroll 1
        for (int i = tid; i < SR * SCF2; i += 256) {
            int r = i / SCF2;
            int c = i - r * SCF2;
            const int g = (row0 + r) * IMG + (col0 + c);
            float xv = __ldg(&Xi[g]);
            float yv = __ldg(&Yi[g]);
            unsigned long long v;
            asm("mov.b64 %0, {%1, %2};" : "=l"(v) : "f"(xv), "f"(yv));
            sxy[r][c] = v;
        }
    } else {
        #pragma unroll 1
        for (int i = tid; i < SR * SCF2; i += 256) {
            int r = i / SCF2;
            int c = i - r * SCF2;
            int gr = row0 + r, gc = col0 + c;
            float xv = 0.0f, yv = 0.0f;
            if ((unsigned)gr < (unsigned)IMG && (unsigned)gc < (unsigned)IMG) {
                xv = __ldg(&Xi[gr * IMG + gc]);
                yv = __ldg(&Yi[gr * IMG + gc]);
            }
            unsigned long long v;
            asm("mov.b64 %0, {%1, %2};" : "=l"(v) : "f"(xv), "f"(yv));
            sxy[r][c] = v;
        }
    }
    __syncthreads();

    const float C1 = 0.0001f, C2 = 0.0009f;
    float lsum = 0.0f;

    #pragma unroll 1
    for (int half = 0; half < 2; half++) {
        const int cbase = half * 32;

        // ------- horizontal streaming FIR: 168 items x 8 outputs -------
        if (tid < SR * 4) {
            const int r  = tid % SR;       // r fastest -> conflict-free STS
            const int o  = tid / SR;       // 0..3
            const int c0 = o * 8;

            unsigned long long acc2[8];
            float accp[8];
            #pragma unroll
            for (int j = 0; j < 8; j++) { acc2[j] = 0ull; accp[j] = 0.0f; }

            const unsigned long long* src = &sxy[r][cbase + c0];
            #pragma unroll
            for (int q = 0; q < 9; q++) {
                ulonglong2 L = *(const ulonglong2*)(src + 2 * q);
                #pragma unroll
                for (int t = 0; t < 2; t++) {
                    const int m = 2 * q + t;
                    unsigned long long v = t ? L.y : L.x;
                    float xl, yh;
                    UNPK(xl, yh, v);
                    float pm = xl * yh;
                    #pragma unroll
                    for (int j = 0; j < 8; j++) {
                        const int k = m - j;
                        if (k >= 0 && k <= 10) {
                            FMA2(acc2[j], v, WP[k], acc2[j]);
                            accp[j] = fmaf(WGs[k], pm, accp[j]);
                        }
                    }
                }
            }
            #pragma unroll
            for (int j = 0; j < 8; j += 2)
                *(ulonglong2*)&hxy[r][c0 + j] = make_ulonglong2(acc2[j], acc2[j + 1]);
            *(float4*)&hp[r][c0]     = make_float4(accp[0], accp[1], accp[2], accp[3]);
            *(float4*)&hp[r][c0 + 4] = make_float4(accp[4], accp[5], accp[6], accp[7]);
        }
        __syncthreads();

        // ------- vertical streaming FIR + SSIM: 32 cols x 8 groups x 4 rows -------
        {
            const int c   = tid & 31;
            const int r0v = (tid >> 5) << 2;

            unsigned long long acc2[4];
            float accp[4];
            #pragma unroll
            for (int j = 0; j < 4; j++) { acc2[j] = 0ull; accp[j] = 0.0f; }

            #pragma unroll
            for (int m = 0; m < 14; m++) {
                unsigned long long v = hxy[r0v + m][c];
                float pm = hp[r0v + m][c];
                #pragma unroll
                for (int j = 0; j < 4; j++) {
                    const int k = m - j;
                    if (k >= 0 && k <= 10) {
                        FMA2(acc2[j], v, WP[k], acc2[j]);
                        accp[j] = fmaf(WGs[k], pm, accp[j]);
                    }
                }
            }
            #pragma unroll
            for (int j = 0; j < 4; j++) {
                float mu1, mu2;
                UNPK(mu1, mu2, acc2[j]);
                float m12 = mu1 * mu2;
                float sig = accp[j] - m12;
                float sq  = mu1 * mu1 + mu2 * mu2;
                float num = (2.0f * m12 + C1) * (2.0f * sig + C2);
                float den = (sq + C1) * (sq + C2);
                lsum += __fdividef(num, den);
            }
        }
        __syncthreads();
    }

    // ---------------- block reduction ----------------
    #pragma unroll
    for (int off = 16; off > 0; off >>= 1)
        lsum += __shfl_xor_sync(0xFFFFFFFFu, lsum, off);
    if ((tid & 31) == 0) wsum[tid >> 5] = lsum;
    __syncthreads();
    if (tid == 0) {
        float v = 0.0f;
        #pragma unroll
        for (int w = 0; w < 8; w++) v += wsum[w];
        int bid = blockIdx.x + GX * (blockIdx.y + GY * blockIdx.z);
        g_partials[bid] = v;
        __threadfence();
        unsigned int ticket = atomicAdd(&g_count, 1u);
        s_last = (ticket == NBLK - 1);
    }
    __syncthreads();

    // ---------------- last block: final reduction ----------------
    if (s_last) {
        float s = 0.0f;
        #pragma unroll 4
        for (int i = tid; i < NBLK; i += 256)
            s += *((volatile float*)&g_partials[i]);
        #pragma unroll
        for (int off = 16; off > 0; off >>= 1)
            s += __shfl_xor_sync(0xFFFFFFFFu, s, off);
        __syncthreads();
        if ((tid & 31) == 0) wsum[tid >> 5] = s;
        __syncthreads();
        if (tid == 0) {
            float v = 0.0f;
            #pragma unroll
            for (int w = 0; w < 8; w++) v += wsum[w];
            out[0]  = v * (1.0f / 8388608.0f);
            g_count = 0;
        }
    }
}

extern "C" void kernel_launch(void* const* d_in, const int* in_sizes, int n_in,
                              void* d_out, int out_size)
{
    (void)in_sizes; (void)n_in; (void)out_size;
    const float* X_gt   = (const float*)d_in[0];
    const float* X_pred = (const float*)d_in[1];
    float* out = (float*)d_out;

    dim3 grid(GX, GY, GZ);
    ssim_fused_kernel<<<grid, 256>>>(X_gt, X_pred, out);
}